// round 16
// baseline (speedup 1.0000x reference)
#include <cuda_runtime.h>
#include <math.h>

#define T_STEPS 1000
#define BATCH   1024
#define IN_DIM  80
#define HID     128
#define OUT_DIM 10
#define WPAD    130            // padded w row stride (even -> LDS.64 aligned)

#define REC_CTAS  148          // one CTA per SM
#define REC_WARPS 7            // 148*7 = 1036 >= 1024 batches

typedef unsigned long long ull;

__device__ float g_xw[(size_t)T_STEPS * BATCH * HID];   // 512 MB scratch

__device__ __forceinline__ ull pk2(float lo, float hi) {
    ull r; asm("mov.b64 %0, {%1, %2};" : "=l"(r) : "f"(lo), "f"(hi)); return r;
}
__device__ __forceinline__ ull ffma2(ull a, ull b, ull c) {
    ull d; asm("fma.rn.f32x2 %0, %1, %2, %3;" : "=l"(d) : "l"(a), "l"(b), "l"(c)); return d;
}
__device__ __forceinline__ ull fadd2(ull a, ull b) {
    ull d; asm("add.rn.f32x2 %0, %1, %2;" : "=l"(d) : "l"(a), "l"(b)); return d;
}

// ---------------------------------------------------------------------------
// Kernel A (R12 verbatim): xw[row][h] = ascending-k single-acc fma.rn.f32x2
// chain. CTA: 128 threads, 64 rows x 128 h; smem 62.3 KB -> 3 CTA/SM.
// ---------------------------------------------------------------------------
__global__ void __launch_bounds__(128) xw_gemm_kernel(const float* __restrict__ x,
                                                      const float* __restrict__ w_in,
                                                      float* __restrict__ xw) {
    extern __shared__ float sm[];
    float* xs = sm;                   // [64][81] padded rows
    float* ws = sm + 64 * 81;         // [80][WPAD] transposed: ws[k*WPAD+h]

    long row0 = (long)blockIdx.x * 64;
    int tid = threadIdx.x;

    const float* xsrc = x + row0 * IN_DIM;
    for (int idx = tid; idx < 64 * IN_DIM; idx += 128) {
        int r = idx / IN_DIM, k = idx - r * IN_DIM;
        xs[r * 81 + k] = xsrc[idx];
    }
    for (int idx = tid; idx < HID * IN_DIM; idx += 128) {
        int h = idx / IN_DIM, k = idx - h * IN_DIM;
        ws[k * WPAD + h] = w_in[idx];
    }
    __syncthreads();

    int hg = tid & 15;        // h-pairs 2hg + 32j (j<4)
    int rg = tid >> 4;        // rows rg + 8i (i<8)

    ull acc[8][4];
#pragma unroll
    for (int i = 0; i < 8; ++i)
#pragma unroll
        for (int j = 0; j < 4; ++j) acc[i][j] = 0ull;

#pragma unroll 10
    for (int k = 0; k < IN_DIM; ++k) {
        ull wp[4];
#pragma unroll
        for (int j = 0; j < 4; ++j)
            wp[j] = *(const ull*)&ws[k * WPAD + 2 * hg + 32 * j];
        float xv[8];
#pragma unroll
        for (int i = 0; i < 8; ++i)
            xv[i] = xs[(rg + 8 * i) * 81 + k];
#pragma unroll
        for (int i = 0; i < 8; ++i) {
            ull xd = pk2(xv[i], xv[i]);
#pragma unroll
            for (int j = 0; j < 4; ++j)
                acc[i][j] = ffma2(xd, wp[j], acc[i][j]);
        }
    }

#pragma unroll
    for (int i = 0; i < 8; ++i) {
        float* dst = &xw[(row0 + rg + 8 * i) * HID];
#pragma unroll
        for (int j = 0; j < 4; ++j)
            *(ull*)&dst[2 * hg + 32 * j] = acc[i][j];
    }
}

// ---------------------------------------------------------------------------
// Kernel B: recurrence, 148 CTAs x 224 threads, warp-per-batch, no barriers.
// Spike walk is SOFTWARE-PIPELINED (depth 2): LDS for spike i+2 issues before
// spike i is consumed, hiding the ~29-cyc smem latency that dominated the
// per-step serial chain. Consumption stays strictly ascending-j with the
// same add.rn.f32x2 / __fadd_rn chains -> bitwise identical output.
// ---------------------------------------------------------------------------
__global__ void __launch_bounds__(224) snn_rec_kernel(const float* __restrict__ xw,
                                                      const float* __restrict__ w_rec,
                                                      const float* __restrict__ w_out,
                                                      float* __restrict__ out) {
    extern __shared__ float smem[];
    float* wr_p = smem;              // [128][128] permuted: wr_p[j*128+4*(h&31)+(h>>5)]
    float* wo_s = smem + HID * HID;  // [128][16]: wo_s[j*16+o] = w_out[o][j]

    int tid = threadIdx.x;
    for (int idx = tid; idx < HID * HID; idx += 224) {
        int h = idx >> 7, j = idx & 127;
        wr_p[(j << 7) + ((h & 31) << 2) + (h >> 5)] = w_rec[idx];
    }
    for (int idx = tid; idx < HID * 16; idx += 224) {
        int j = idx >> 4, o = idx & 15;
        wo_s[idx] = (o < OUT_DIM) ? w_out[o * HID + j] : 0.0f;
    }
    __syncthreads();

    int warp = tid >> 5, lane = tid & 31;
    int batch = blockIdx.x * REC_WARPS + warp;
    if (batch >= BATCH) return;

    float v0 = 0.f, v1 = 0.f, v2 = 0.f, v3 = 0.f;
    float c0 = 0.f, c1 = 0.f, c2 = 0.f, c3 = 0.f;
    float vo = 0.f, io = 0.f;

    const float* xwp = xw + (size_t)batch * HID + lane;

    // xw prefetch pipeline, distance 2
    float x0 = xwp[0], x1 = xwp[32], x2 = xwp[64], x3 = xwp[96];
    const float* p1 = xwp + (size_t)(BATCH * HID);
    float a0 = p1[0], a1 = p1[32], a2 = p1[64], a3 = p1[96];

    const float* wr_l = wr_p + (lane << 2);   // this lane's 4-weight column base
    const float* wo_l = wo_s + lane;

    for (int t = 0; t < T_STEPS; ++t) {
        // --- LIF (exact reference expression order, separate rounding) ---
        float vd0 = __fadd_rn(v0, __fmul_rn(0.1f, __fadd_rn(__fsub_rn(0.f, v0), c0)));
        float vd1 = __fadd_rn(v1, __fmul_rn(0.1f, __fadd_rn(__fsub_rn(0.f, v1), c1)));
        float vd2 = __fadd_rn(v2, __fmul_rn(0.1f, __fadd_rn(__fsub_rn(0.f, v2), c2)));
        float vd3 = __fadd_rn(v3, __fmul_rn(0.1f, __fadd_rn(__fsub_rn(0.f, v3), c3)));
        float id0 = __fsub_rn(c0, __fmul_rn(0.2f, c0));
        float id1 = __fsub_rn(c1, __fmul_rn(0.2f, c1));
        float id2 = __fsub_rn(c2, __fmul_rn(0.2f, c2));
        float id3 = __fsub_rn(c3, __fmul_rn(0.2f, c3));
        bool z0 = __fsub_rn(vd0, 1.0f) > 0.0f;
        bool z1 = __fsub_rn(vd1, 1.0f) > 0.0f;
        bool z2 = __fsub_rn(vd2, 1.0f) > 0.0f;
        bool z3 = __fsub_rn(vd3, 1.0f) > 0.0f;
        v0 = z0 ? 0.f : vd0;
        v1 = z1 ? 0.f : vd1;
        v2 = z2 ? 0.f : vd2;
        v3 = z3 ? 0.f : vd3;

        unsigned m0 = __ballot_sync(0xffffffffu, z0);
        unsigned m1 = __ballot_sync(0xffffffffu, z1);
        unsigned m2 = __ballot_sync(0xffffffffu, z2);
        unsigned m3 = __ballot_sync(0xffffffffu, z3);
        ull lo = (ull)m0 | ((ull)m1 << 32);   // spikes j in [0,64)
        ull hi = (ull)m2 | ((ull)m3 << 32);   // spikes j in [64,128)

        // prefetch xw[t+2] (clamped)
        int t2 = (t + 2 < T_STEPS) ? t + 2 : T_STEPS - 1;
        const float* p2 = xwp + (size_t)t2 * (BATCH * HID);
        float b0f = p2[0], b1f = p2[32], b2f = p2[64], b3f = p2[96];

        // --- sparse z @ w_rec.T, ascending j, depth-2 pipelined walk ---
        // (masks are warp-uniform -> uniform branches, no divergence)
        int cnt = __popcll(lo) + __popcll(hi);
        ull r01 = 0ull, r23 = 0ull;
        float os = 0.f;

#define NEXTJ(J) do {                                              \
        if (lo) { J = __ffsll(lo) - 1; lo &= lo - 1; }             \
        else    { J = 64 + __ffsll(hi) - 1; hi &= hi - 1; }        \
    } while (0)

        ulonglong2 buf0 = {0ull, 0ull}, buf1 = {0ull, 0ull};
        float ob0 = 0.f, ob1 = 0.f;
        int j;
        if (cnt > 0) {
            NEXTJ(j);
            buf0 = *(const ulonglong2*)(wr_l + (j << 7));
            if (lane < OUT_DIM) ob0 = wo_l[j << 4];
        }
        if (cnt > 1) {
            NEXTJ(j);
            buf1 = *(const ulonglong2*)(wr_l + (j << 7));
            if (lane < OUT_DIM) ob1 = wo_l[j << 4];
        }
        for (int i = 0; i < cnt - 2; ++i) {
            NEXTJ(j);
            ulonglong2 bn = *(const ulonglong2*)(wr_l + (j << 7));  // issue ahead
            float obn = 0.f;
            if (lane < OUT_DIM) obn = wo_l[j << 4];
            r01 = fadd2(r01, buf0.x);          // consume ~2-iter-old load
            r23 = fadd2(r23, buf0.y);
            if (lane < OUT_DIM) os = __fadd_rn(os, ob0);
            buf0 = buf1; ob0 = ob1;
            buf1 = bn;   ob1 = obn;
        }
        if (cnt > 0) {
            r01 = fadd2(r01, buf0.x);
            r23 = fadd2(r23, buf0.y);
            if (lane < OUT_DIM) os = __fadd_rn(os, ob0);
        }
        if (cnt > 1) {
            r01 = fadd2(r01, buf1.x);
            r23 = fadd2(r23, buf1.y);
            if (lane < OUT_DIM) os = __fadd_rn(os, ob1);
        }
#undef NEXTJ

        float r0, r1, r2, r3;
        asm("mov.b64 {%0, %1}, %2;" : "=f"(r0), "=f"(r1) : "l"(r01));
        asm("mov.b64 {%0, %1}, %2;" : "=f"(r2), "=f"(r3) : "l"(r23));

        c0 = __fadd_rn(__fadd_rn(id0, x0), r0);
        c1 = __fadd_rn(__fadd_rn(id1, x1), r1);
        c2 = __fadd_rn(__fadd_rn(id2, x2), r2);
        c3 = __fadd_rn(__fadd_rn(id3, x3), r3);

        // --- LI readout (lanes 0..9, o = lane) ---
        if (lane < OUT_DIM) {
            float ij = __fadd_rn(io, os);
            vo = __fadd_rn(vo, __fmul_rn(0.1f, __fadd_rn(__fsub_rn(0.f, vo), ij)));
            io = __fsub_rn(ij, __fmul_rn(0.2f, ij));
        }

        x0 = a0; x1 = a1; x2 = a2; x3 = a3;
        a0 = b0f; a1 = b1f; a2 = b2f; a3 = b3f;
    }

    // --- log_softmax over 10 outputs (ascending-o chains) ---
    float mx = -INFINITY;
#pragma unroll
    for (int o = 0; o < OUT_DIM; ++o)
        mx = fmaxf(mx, __shfl_sync(0xffffffffu, vo, o));
    float s = 0.f;
#pragma unroll
    for (int o = 0; o < OUT_DIM; ++o)
        s = __fadd_rn(s, expf(__fsub_rn(__shfl_sync(0xffffffffu, vo, o), mx)));
    if (lane < OUT_DIM)
        out[batch * OUT_DIM + lane] = __fsub_rn(__fsub_rn(vo, mx), logf(s));
}

// ---------------------------------------------------------------------------
extern "C" void kernel_launch(void* const* d_in, const int* in_sizes, int n_in,
                              void* d_out, int out_size) {
    const float* x     = (const float*)d_in[0];
    const float* w_in  = (const float*)d_in[1];
    const float* w_rec = (const float*)d_in[2];
    const float* w_out = (const float*)d_in[3];
    float* out = (float*)d_out;

    float* xw = nullptr;
    cudaGetSymbolAddress((void**)&xw, g_xw);

    // GEMM smem: 64*81 + 80*130 floats = 62.3 KB -> 3 CTA/SM
    size_t gemm_smem = (size_t)(64 * 81 + IN_DIM * WPAD) * sizeof(float);
    cudaFuncSetAttribute(xw_gemm_kernel, cudaFuncAttributeMaxDynamicSharedMemorySize,
                         (int)gemm_smem);
    xw_gemm_kernel<<<16000, 128, gemm_smem>>>(x, w_in, xw);

    size_t rec_smem = (size_t)(HID * HID + HID * 16) * sizeof(float);
    cudaFuncSetAttribute(snn_rec_kernel, cudaFuncAttributeMaxDynamicSharedMemorySize,
                         (int)rec_smem);
    snn_rec_kernel<<<REC_CTAS, REC_WARPS * 32, rec_smem>>>(xw, w_rec, w_out, out);
}